// round 15
// baseline (speedup 1.0000x reference)
#include <cuda_runtime.h>
#include <cuda_fp16.h>
#include <cstdint>

#define BB 4
#define SS 2048
#define DD 1024
#define HH 16
#define DKK 64
#define MR (BB*SS)   // 8192

#define MT 128
#define NT 128
#define NCH 32
#define TILEH 4096           // halves per 128x32 tile
#define TILEB 8192           // bytes per tile
#define CHB (4*TILEB)        // stage: Ahi|Alo|Bhi|Blo = 32KB
#define NSTG 3
#define KVP 16               // kv_outer partials

// ---------------- device scratch ----------------
__device__ __half g_wt[4][2][DD*DD];    // weight panels (x32 scaled, split hi/lo)
__device__ __half g_pan[4][2][MR*DD];   // activation panels: 0=q 1=k 2=v 3=softmax-out
__device__ float g_qh[MR*DD];
__device__ float g_kh[MR*DD];
__device__ float g_vh[MR*DD];
__device__ float g_Mpart[BB*HH*KVP][DKK*DKK];
__device__ float g_M[BB*HH][DKK*DKK];
__device__ int g_cnt[BB*HH];            // zero-init tickets (reset in-kernel)

// ---------------- helpers ----------------
__device__ __forceinline__ uint32_t smem_u32(const void* p) {
    uint32_t a;
    asm("{ .reg .u64 t; cvta.to.shared.u64 t, %1; cvt.u32.u64 %0, t; }" : "=r"(a) : "l"(p));
    return a;
}
#define MBAR_INIT(a, c) asm volatile("mbarrier.init.shared.b64 [%0], %1;" :: "r"(a), "r"(c) : "memory")
#define MBAR_WAIT(a, ph) do { \
    asm volatile("{\n\t.reg .pred P;\n\tWL%=:\n\t" \
        "mbarrier.try_wait.parity.shared.b64 P, [%0], %1;\n\t" \
        "@!P bra WL%=;\n\t}" :: "r"(a), "r"(ph) : "memory"); } while (0)
#define EXPECT_TX(a, n) asm volatile( \
    "mbarrier.arrive.expect_tx.shared.b64 _, [%0], %1;" :: "r"(a), "r"(n) : "memory")
#define BULK(dst, src, n, bar) asm volatile( \
    "cp.async.bulk.shared::cluster.global.mbarrier::complete_tx::bytes [%0], [%1], %2, [%3];" \
    :: "r"(dst), "l"(src), "r"(n), "r"(bar) : "memory")
#define LDSM4(r, a) asm volatile( \
    "ldmatrix.sync.aligned.m8n8.x4.shared.b16 {%0,%1,%2,%3}, [%4];" \
    : "=r"((r)[0]), "=r"((r)[1]), "=r"((r)[2]), "=r"((r)[3]) : "r"(a))
#define LDSM4T(r, a) asm volatile( \
    "ldmatrix.sync.aligned.m8n8.x4.trans.shared.b16 {%0,%1,%2,%3}, [%4];" \
    : "=r"((r)[0]), "=r"((r)[1]), "=r"((r)[2]), "=r"((r)[3]) : "r"(a))
#define MMAF16(d, a, b0, b1) asm volatile( \
    "mma.sync.aligned.m16n8k16.row.col.f32.f16.f16.f32 " \
    "{%0,%1,%2,%3}, {%4,%5,%6,%7}, {%8,%9}, {%0,%1,%2,%3};" \
    : "+f"((d)[0]), "+f"((d)[1]), "+f"((d)[2]), "+f"((d)[3]) \
    : "r"((a)[0]), "r"((a)[1]), "r"((a)[2]), "r"((a)[3]), "r"(b0), "r"(b1))

__device__ __forceinline__ uint32_t sw64(uint32_t off)  { return off ^ ((off >> 3) & 0x30); }
__device__ __forceinline__ uint32_t sw128(uint32_t off) { return off ^ ((off >> 3) & 0x70); }

__device__ __forceinline__ uint2 split4(float4 f, uint2& lo_out) {
    __half h0 = __float2half_rn(f.x), h1 = __float2half_rn(f.y);
    __half h2 = __float2half_rn(f.z), h3 = __float2half_rn(f.w);
    __half l0 = __float2half_rn(f.x - __half2float(h0));
    __half l1 = __float2half_rn(f.y - __half2float(h1));
    __half l2 = __float2half_rn(f.z - __half2float(h2));
    __half l3 = __float2half_rn(f.w - __half2float(h3));
    __half2 p0 = __halves2half2(h0, h1), p1 = __halves2half2(h2, h3);
    __half2 q0 = __halves2half2(l0, l1), q1 = __halves2half2(l2, l3);
    uint2 hi; hi.x = *(uint32_t*)&p0; hi.y = *(uint32_t*)&p1;
    lo_out.x = *(uint32_t*)&q0; lo_out.y = *(uint32_t*)&q1;
    return hi;
}

// ---------------------------------------------------------------------------
// fused prep:
//   blocks [0, 1024): one (tensor, head, 64-kq tile) each — smem transpose
//   blocks [1024, 5120): q/k/v split (coalesced both ways)
// ---------------------------------------------------------------------------
__global__ void prep_all(const float* __restrict__ wq, const float* __restrict__ wk,
                         const float* __restrict__ wv, const float* __restrict__ wo,
                         const float* __restrict__ q, const float* __restrict__ k,
                         const float* __restrict__ v) {
    int tid = threadIdx.x;
    if (blockIdx.x < 1024) {
        __shared__ float tile[64][65];
        int w = blockIdx.x >> 8;
        int h = (blockIdx.x >> 4) & 15;
        int kq0 = (blockIdx.x & 15) * 64;
        const float* W = (w == 0) ? wq : (w == 1) ? wk : (w == 2) ? wv : wo;
        if (w < 3) {
            #pragma unroll
            for (int i = 0; i < 16; i++) {
                int idx = tid + i * 256;
                int kqr = idx >> 6, dk = idx & 63;
                tile[dk][kqr] = W[h * (DD * DKK) + (kq0 + kqr) * DKK + dk];
            }
        } else {
            #pragma unroll
            for (int i = 0; i < 16; i++) {
                int idx = tid + i * 256;
                int dk = idx >> 6, kqr = idx & 63;
                tile[dk][kqr] = W[(h * 64 + dk) * DD + kq0 + kqr];
            }
        }
        __syncthreads();
        #pragma unroll
        for (int i = 0; i < 2; i++) {
            int idx = tid + i * 256;
            int dk = idx >> 3, chk = idx & 7;
            int kq = kq0 + chk * 8;
            int n = h * 64 + dk;
            float f[8];
            #pragma unroll
            for (int e = 0; e < 8; e++) f[e] = tile[dk][chk * 8 + e] * 32.0f;
            __half hi[8], lo[8];
            #pragma unroll
            for (int e = 0; e < 8; e++) {
                hi[e] = __float2half_rn(f[e]);
                lo[e] = __float2half_rn(f[e] - __half2float(hi[e]));
            }
            uint32_t off = (n & 127) * 64 + (kq & 31) * 2;
            size_t d = ((size_t)((n >> 7) * 32 + (kq >> 5))) * TILEH + (sw64(off) >> 1);
            *(uint4*)&g_wt[w][0][d] = *(uint4*)hi;
            *(uint4*)&g_wt[w][1][d] = *(uint4*)lo;
        }
    } else {
        int idx = (blockIdx.x - 1024) * 256 + tid;
        int m = idx >> 7;
        int k0 = (idx & 127) << 3;
        uint32_t off = (m & 127) * 64 + (k0 & 31) * 2;
        size_t d = ((size_t)((m >> 7) * 32 + (k0 >> 5))) * TILEH + (sw64(off) >> 1);
        size_t s = (size_t)m * DD + k0;
        const float* srcs[3] = { q + s, k + s, v + s };
        #pragma unroll
        for (int w = 0; w < 3; w++) {
            float f[8];
            *(float4*)&f[0] = *(const float4*)(srcs[w]);
            *(float4*)&f[4] = *(const float4*)(srcs[w] + 4);
            __half hi[8], lo[8];
            #pragma unroll
            for (int i = 0; i < 8; i++) {
                hi[i] = __float2half_rn(f[i]);
                lo[i] = __float2half_rn(f[i] - __half2float(hi[i]));
            }
            *(uint4*)&g_pan[w][0][d] = *(uint4*)hi;
            *(uint4*)&g_pan[w][1][d] = *(uint4*)lo;
        }
    }
}

// ---------------------------------------------------------------------------
// split fp16 mma.sync GEMM (unchanged)
// ---------------------------------------------------------------------------
__global__ __launch_bounds__(256, 2) void mma_gemm(
        const float* __restrict__ b0p, const float* __restrict__ b1p,
        const float* __restrict__ b2p, const float* __restrict__ bwp,
        float* __restrict__ Oout, int mode) {
    extern __shared__ char smem[];
    int widx, nIdx;
    const float* bias;
    float* C;
    if (mode == 0) {
        widx = blockIdx.x >> 3;
        nIdx = blockIdx.x & 7;
        bias = (widx == 0) ? b0p : (widx == 1) ? b1p : b2p;
        C = (widx == 0) ? g_qh : (widx == 1) ? g_kh : g_vh;
    } else {
        widx = 3;
        nIdx = blockIdx.x;
        bias = bwp;
        C = Oout;
    }
    const __half* Ahi = g_pan[widx][0];
    const __half* Alo = g_pan[widx][1];
    const __half* Bhi = g_wt[widx][0];
    const __half* Blo = g_wt[widx][1];

    const uint32_t s0 = smem_u32(smem);
    const uint32_t mb = s0 + NSTG * CHB;

    const int tid = threadIdx.x;
    const int wid = tid >> 5, lane = tid & 31;
    const int bm = blockIdx.y * MT, bn = nIdx * NT;
    const int m0 = (wid >> 2) * 64;
    const int n0 = (wid & 3) * 32;

    if (tid == 0) { MBAR_INIT(mb, 1); MBAR_INIT(mb + 8, 1); MBAR_INIT(mb + 16, 1); }
    __syncthreads();

    const uint32_t stage_bytes = (mode == 0) ? 4u * TILEB : 3u * TILEB;
    auto issue = [&](int ch, int stg) {
        uint32_t sb = s0 + stg * CHB;
        uint32_t bar = mb + stg * 8;
        EXPECT_TX(bar, stage_bytes);
        const __half* a0 = Ahi + ((size_t)(blockIdx.y * 32 + ch)) * TILEH;
        const __half* w0 = Bhi + ((size_t)(nIdx * 32 + ch)) * TILEH;
        const __half* w1 = Blo + ((size_t)(nIdx * 32 + ch)) * TILEH;
        BULK(sb,             a0, TILEB, bar);
        if (mode == 0) {
            const __half* a1 = Alo + ((size_t)(blockIdx.y * 32 + ch)) * TILEH;
            BULK(sb + TILEB, a1, TILEB, bar);
        }
        BULK(sb + 2 * TILEB, w0, TILEB, bar);
        BULK(sb + 3 * TILEB, w1, TILEB, bar);
    };
    if (tid == 0) { issue(0, 0); issue(1, 1); }

    const int rowA = m0 + (lane & 7) + ((lane >> 3) & 1) * 8;
    const uint32_t cA = ((lane >> 4) & 1) * 16;
    const uint32_t xswA = (uint32_t)(rowA & 6) << 3;
    const uint32_t aRow = (uint32_t)rowA * 64;
    const int rowB = n0 + ((lane >> 4) << 3) + (lane & 7);
    const uint32_t cB = ((lane >> 3) & 1) * 16;
    const uint32_t xswB = (uint32_t)(rowB & 6) << 3;
    const uint32_t bRow = (uint32_t)rowB * 64;

    float acc[4][4][4];
    #pragma unroll
    for (int i = 0; i < 4; i++)
        #pragma unroll
        for (int j = 0; j < 4; j++)
            #pragma unroll
            for (int r = 0; r < 4; r++) acc[i][j][r] = 0.0f;

    for (int c = 0; c < NCH; ++c) {
        int stg = c % 3;
        uint32_t sb = s0 + stg * CHB;
        MBAR_WAIT(mb + stg * 8, (c / 3) & 1);
        if (tid == 0 && c + 2 < NCH) issue(c + 2, (c + 2) % 3);

        #pragma unroll
        for (int ks = 0; ks < 2; ks++) {
            const uint32_t aoff = aRow + (((uint32_t)(ks * 32) + cA) ^ xswA);
            const uint32_t boff = bRow + (((uint32_t)(ks * 32) + cB) ^ xswB);
            uint32_t ah[4][4], al[4][4], bh[2][4], bl[2][4];
            #pragma unroll
            for (int i = 0; i < 4; i++) LDSM4(ah[i], sb + aoff + i * 1024);
            #pragma unroll
            for (int g = 0; g < 2; g++) LDSM4(bh[g], sb + 2 * TILEB + boff + g * 1024);
            #pragma unroll
            for (int i = 0; i < 4; i++) {
                MMAF16(acc[i][0], ah[i], bh[0][0], bh[0][1]);
                MMAF16(acc[i][1], ah[i], bh[0][2], bh[0][3]);
                MMAF16(acc[i][2], ah[i], bh[1][0], bh[1][1]);
                MMAF16(acc[i][3], ah[i], bh[1][2], bh[1][3]);
            }
            #pragma unroll
            for (int g = 0; g < 2; g++) LDSM4(bl[g], sb + 3 * TILEB + boff + g * 1024);
            #pragma unroll
            for (int i = 0; i < 4; i++) {
                MMAF16(acc[i][0], ah[i], bl[0][0], bl[0][1]);
                MMAF16(acc[i][1], ah[i], bl[0][2], bl[0][3]);
                MMAF16(acc[i][2], ah[i], bl[1][0], bl[1][1]);
                MMAF16(acc[i][3], ah[i], bl[1][2], bl[1][3]);
            }
            if (mode == 0) {
                #pragma unroll
                for (int i = 0; i < 4; i++) LDSM4(al[i], sb + TILEB + aoff + i * 1024);
                #pragma unroll
                for (int i = 0; i < 4; i++) {
                    MMAF16(acc[i][0], al[i], bh[0][0], bh[0][1]);
                    MMAF16(acc[i][1], al[i], bh[0][2], bh[0][3]);
                    MMAF16(acc[i][2], al[i], bh[1][0], bh[1][1]);
                    MMAF16(acc[i][3], al[i], bh[1][2], bh[1][3]);
                }
            }
        }
        __syncthreads();
    }

    #pragma unroll
    for (int i = 0; i < 4; i++) {
        int row0 = bm + m0 + i * 16 + (lane >> 2);
        #pragma unroll
        for (int jj = 0; jj < 4; jj++) {
            int col = bn + n0 + jj * 8 + (lane & 3) * 2;
            float2 bv = *(const float2*)(bias + col);
            float2 r0, r1;
            r0.x = acc[i][jj][0] * 0.03125f + bv.x;  r0.y = acc[i][jj][1] * 0.03125f + bv.y;
            r1.x = acc[i][jj][2] * 0.03125f + bv.x;  r1.y = acc[i][jj][3] * 0.03125f + bv.y;
            *(float2*)(C + (size_t)row0 * DD + col) = r0;
            *(float2*)(C + (size_t)(row0 + 8) * DD + col) = r1;
        }
    }
}

// ---------------------------------------------------------------------------
// kv_outer + fused last-block reduce: M[bh] = sum of 16 partials (fixed order)
// ---------------------------------------------------------------------------
__global__ __launch_bounds__(128) void kv_outer_mma() {
    extern __shared__ char smem[];
    const uint32_t sK0 = smem_u32(smem);
    const uint32_t sK1 = sK0 + 16384;
    const uint32_t sV0 = sK0 + 32768;
    const uint32_t sV1 = sK0 + 49152;

    int bh = blockIdx.x;
    int b = bh >> 4, h = bh & 15;
    int sy = blockIdx.y;
    int tid = threadIdx.x;
    int wid = tid >> 5, lane = tid & 31;
    int wm = wid >> 1, wn = wid & 1;

    const float* Kg = g_kh + ((size_t)b * SS + sy * 128) * DD + h * DKK;
    const float* Vg = g_vh + ((size_t)b * SS + sy * 128) * DD + h * DKK;

    #pragma unroll
    for (int i = 0; i < 16; i++) {
        int idx = tid + i * 128;
        int s = idx >> 4, c4 = (idx & 15) << 2;
        uint32_t sw = sw128((uint32_t)s * 128 + c4 * 2);
        uint2 lo;
        uint2 hi = split4(*(const float4*)(Kg + (size_t)s * DD + c4), lo);
        *(uint2*)(smem + sw) = hi;
        *(uint2*)(smem + 16384 + sw) = lo;
        hi = split4(*(const float4*)(Vg + (size_t)s * DD + c4), lo);
        *(uint2*)(smem + 32768 + sw) = hi;
        *(uint2*)(smem + 49152 + sw) = lo;
    }
    __syncthreads();

    const uint32_t a_srow = (uint32_t)((lane & 7) + ((lane >> 4) << 3));
    const uint32_t a_xsw = (a_srow & 7) << 4;
    uint32_t aOff[2];
    #pragma unroll
    for (int mi = 0; mi < 2; mi++) {
        uint32_t col = (uint32_t)(wm * 32 + mi * 16 + ((lane >> 3) & 1) * 8);
        aOff[mi] = a_srow * 128 + ((col * 2) ^ a_xsw);
    }
    const uint32_t b_srow = (uint32_t)((lane & 7) + (((lane >> 3) & 1) << 3));
    const uint32_t b_xsw = (b_srow & 7) << 4;
    uint32_t bOff[2];
    #pragma unroll
    for (int g = 0; g < 2; g++) {
        uint32_t col = (uint32_t)(wn * 32 + g * 16 + ((lane >> 4) & 1) * 8);
        bOff[g] = b_srow * 128 + ((col * 2) ^ b_xsw);
    }

    float acc[2][4][4];
    #pragma unroll
    for (int i = 0; i < 2; i++)
        #pragma unroll
        for (int j = 0; j < 4; j++)
            #pragma unroll
            for (int r = 0; r < 4; r++) acc[i][j][r] = 0.0f;

    #pragma unroll
    for (int st = 0; st < 8; st++) {
        uint32_t base = (uint32_t)st * 2048;
        uint32_t kh[2][4], kl[2][4], vh[2][4], vl[2][4];
        #pragma unroll
        for (int mi = 0; mi < 2; mi++) LDSM4T(kh[mi], sK0 + base + aOff[mi]);
        #pragma unroll
        for (int g = 0; g < 2; g++)  LDSM4T(vh[g], sV0 + base + bOff[g]);
        #pragma unroll
        for (int mi = 0; mi < 2; mi++) {
            MMAF16(acc[mi][0], kh[mi], vh[0][0], vh[0][1]);
            MMAF16(acc[mi][1], kh[mi], vh[0][2], vh[0][3]);
            MMAF16(acc[mi][2], kh[mi], vh[1][0], vh[1][1]);
            MMAF16(acc[mi][3], kh[mi], vh[1][2], vh[1][3]);
        }
        #pragma unroll
        for (int g = 0; g < 2; g++)  LDSM4T(vl[g], sV1 + base + bOff[g]);
        #pragma unroll
        for (int mi = 0; mi < 2; mi++) {
            MMAF16(acc[mi][0], kh[mi], vl[0][0], vl[0][1]);
            MMAF16(acc[mi][1], kh[mi], vl[0][2], vl[0][3]);
            MMAF16(acc[mi][2], kh[mi], vl[1][0], vl[1][1]);
            MMAF16(acc[mi][3], kh[mi], vl[1][2], vl[1][3]);
        }
        #pragma unroll
        for (int mi = 0; mi < 2; mi++) LDSM4T(kl[mi], sK1 + base + aOff[mi]);
        #pragma unroll
        for (int mi = 0; mi < 2; mi++) {
            MMAF16(acc[mi][0], kl[mi], vh[0][0], vh[0][1]);
            MMAF16(acc[mi][1], kl[mi], vh[0][2], vh[0][3]);
            MMAF16(acc[mi][2], kl[mi], vh[1][0], vh[1][1]);
            MMAF16(acc[mi][3], kl[mi], vh[1][2], vh[1][3]);
        }
    }

    float* Mout = g_Mpart[bh * KVP + sy];
    #pragma unroll
    for (int mi = 0; mi < 2; mi++) {
        int row = wm * 32 + mi * 16 + (lane >> 2);
        #pragma unroll
        for (int ng = 0; ng < 4; ng++) {
            int col = wn * 32 + ng * 8 + (lane & 3) * 2;
            float2 p0, p1;
            p0.x = acc[mi][ng][0]; p0.y = acc[mi][ng][1];
            p1.x = acc[mi][ng][2]; p1.y = acc[mi][ng][3];
            *(float2*)&Mout[row * DKK + col]       = p0;
            *(float2*)&Mout[(row + 8) * DKK + col] = p1;
        }
    }

    // ---- last-block-per-bh reduction (fixed-order sum => deterministic) ----
    __threadfence();
    __shared__ int s_last;
    __syncthreads();
    if (tid == 0) s_last = (atomicAdd(&g_cnt[bh], 1) == KVP - 1) ? 1 : 0;
    __syncthreads();
    if (s_last) {
        __threadfence();   // acquire: all partials visible
        // 4096 floats / 128 threads = 8 float4 per thread
        #pragma unroll
        for (int i = 0; i < 8; i++) {
            int e4 = tid + i * 128;
            float4 s = make_float4(0.f, 0.f, 0.f, 0.f);
            #pragma unroll
            for (int c = 0; c < KVP; c++) {
                float4 p = *(const float4*)&g_Mpart[bh * KVP + c][e4 * 4];
                s.x += p.x; s.y += p.y; s.z += p.z; s.w += p.w;
            }
            *(float4*)&g_M[bh][e4 * 4] = s;
        }
        if (tid == 0) g_cnt[bh] = 0;   // reset for graph replay
    }
}

// ---------------------------------------------------------------------------
// qm_softmax via tensor cores (unchanged)
// ---------------------------------------------------------------------------
__global__ __launch_bounds__(256) void qm_softmax_mma() {
    extern __shared__ char smem[];
    const uint32_t sQ0 = smem_u32(smem);
    const uint32_t sQ1 = sQ0 + 16384;
    const uint32_t sM0 = sQ0 + 32768;
    const uint32_t sM1 = sQ0 + 40960;

    int bh = blockIdx.x;
    int b = bh >> 4, h = bh & 15;
    int sy = blockIdx.y;
    int tid = threadIdx.x;
    int wid = tid >> 5, lane = tid & 31;

    #pragma unroll
    for (int i = 0; i < 4; i++) {
        int idx = tid + i * 256;
        int j = idx >> 4, c4 = (idx & 15) << 2;
        uint32_t sw = sw128((uint32_t)j * 128 + c4 * 2);
        uint2 lo;
        uint2 hi = split4(*(const float4*)&g_M[bh][j * DKK + c4], lo);
        *(uint2*)(smem + 32768 + sw) = hi;
        *(uint2*)(smem + 40960 + sw) = lo;
    }
    const float* Qg = g_qh + ((size_t)b * SS + sy * 128) * DD + h * DKK;
    #pragma unroll
    for (int i = 0; i < 8; i++) {
        int idx = tid + i * 256;
        int s = idx >> 4, c4 = (idx & 15) << 2;
        uint32_t sw = sw128((uint32_t)s * 128 + c4 * 2);
        uint2 lo;
        uint2 hi = split4(*(const float4*)(Qg + (size_t)s * DD + c4), lo);
        *(uint2*)(smem + sw) = hi;
        *(uint2*)(smem + 16384 + sw) = lo;
    }
    __syncthreads();

    const int a_row = wid * 16 + (lane & 7) + ((lane >> 3) & 1) * 8;
    const uint32_t a_base = (uint32_t)a_row * 128;
    const uint32_t a_xsw = ((uint32_t)a_row & 7) << 4;
    const uint32_t a_c = ((lane >> 4) & 1) * 16;
    const uint32_t b_srow = (uint32_t)((lane & 7) + (((lane >> 3) & 1) << 3));
    const uint32_t b_xsw = (b_srow & 7) << 4;
    uint32_t bOff[4];
    #pragma unroll
    for (int g = 0; g < 4; g++) {
        uint32_t col = (uint32_t)(g * 16 + ((lane >> 4) & 1) * 8);
        bOff[g] = b_srow * 128 + ((col * 2) ^ b_xsw);
    }

    float acc[8][4];
    #pragma unroll
    for (int j = 0; j < 8; j++)
        #pragma unroll
        for (int r = 0; r < 4; r++) acc[j][r] = 0.0f;

    #pragma unroll
    for (int st = 0; st < 4; st++) {
        uint32_t aoff = a_base + (((uint32_t)st * 32 + a_c) ^ a_xsw);
        uint32_t bbase = (uint32_t)st * 2048;
        uint32_t qh4[4], ql4[4], mh[4][4], ml[4][4];
        LDSM4(qh4, sQ0 + aoff);
        #pragma unroll
        for (int g = 0; g < 4; g++) LDSM4T(mh[g], sM0 + bbase + bOff[g]);
        #pragma unroll
        for (int g = 0; g < 4; g++) {
            MMAF16(acc[g * 2 + 0], qh4, mh[g][0], mh[g][1]);
            MMAF16(acc[g * 2 + 1], qh4, mh[g][2], mh[g][3]);
        }
        #pragma unroll
        for (int g = 0; g < 4; g++) LDSM4T(ml[g], sM1 + bbase + bOff[g]);
        #pragma unroll
        for (int g = 0; g < 4; g++) {
            MMAF16(acc[g * 2 + 0], qh4, ml[g][0], ml[g][1]);
            MMAF16(acc[g * 2 + 1], qh4, ml[g][2], ml[g][3]);
        }
        LDSM4(ql4, sQ1 + aoff);
        #pragma unroll
        for (int g = 0; g < 4; g++) {
            MMAF16(acc[g * 2 + 0], ql4, mh[g][0], mh[g][1]);
            MMAF16(acc[g * 2 + 1], ql4, mh[g][2], mh[g][3]);
        }
    }

    float mx0 = -1e30f, mx1 = -1e30f;
    #pragma unroll
    for (int f = 0; f < 8; f++) {
        acc[f][0] *= 0.125f; acc[f][1] *= 0.125f;
        acc[f][2] *= 0.125f; acc[f][3] *= 0.125f;
        mx0 = fmaxf(mx0, fmaxf(acc[f][0], acc[f][1]));
        mx1 = fmaxf(mx1, fmaxf(acc[f][2], acc[f][3]));
    }
    #pragma unroll
    for (int o = 1; o <= 2; o <<= 1) {
        mx0 = fmaxf(mx0, __shfl_xor_sync(0xffffffffu, mx0, o));
        mx1 = fmaxf(mx1, __shfl_xor_sync(0xffffffffu, mx1, o));
    }
    float sm0 = 0.0f, sm1 = 0.0f;
    #pragma unroll
    for (int f = 0; f < 8; f++) {
        acc[f][0] = __expf(acc[f][0] - mx0); acc[f][1] = __expf(acc[f][1] - mx0);
        acc[f][2] = __expf(acc[f][2] - mx1); acc[f][3] = __expf(acc[f][3] - mx1);
        sm0 += acc[f][0] + acc[f][1];
        sm1 += acc[f][2] + acc[f][3];
    }
    #pragma unroll
    for (int o = 1; o <= 2; o <<= 1) {
        sm0 += __shfl_xor_sync(0xffffffffu, sm0, o);
        sm1 += __shfl_xor_sync(0xffffffffu, sm1, o);
    }
    float inv0 = 1.0f / sm0, inv1 = 1.0f / sm1;

    int mt = b * 16 + sy;
    int prow0 = wid * 16 + (lane >> 2);
    #pragma unroll
    for (int f = 0; f < 8; f++) {
        int cc = f * 8 + (lane & 3) * 2;
        int chunk = 2 * h + (cc >> 5);
        uint32_t cwi = (uint32_t)(cc & 31);
        size_t tbase = ((size_t)(mt * 32 + chunk)) * TILEH;
        uint32_t off0 = sw64((uint32_t)prow0 * 64 + cwi * 2) >> 1;
        uint32_t off1 = sw64((uint32_t)(prow0 + 8) * 64 + cwi * 2) >> 1;
        __half2 v0 = __halves2half2(__float2half_rn(acc[f][0] * inv0),
                                    __float2half_rn(acc[f][1] * inv0));
        __half2 v1 = __halves2half2(__float2half_rn(acc[f][2] * inv1),
                                    __float2half_rn(acc[f][3] * inv1));
        *(__half2*)&g_pan[3][0][tbase + off0] = v0;
        *(__half2*)&g_pan[3][0][tbase + off1] = v1;
    }
}

// ---------------------------------------------------------------------------
extern "C" void kernel_launch(void* const* d_in, const int* in_sizes, int n_in,
                              void* d_out, int out_size) {
    const float* q    = (const float*)d_in[0];
    const float* k    = (const float*)d_in[1];
    const float* v    = (const float*)d_in[2];
    const float* wq_w = (const float*)d_in[3];
    const float* wq_b = (const float*)d_in[4];
    const float* wk_w = (const float*)d_in[5];
    const float* wk_b = (const float*)d_in[6];
    const float* wv_w = (const float*)d_in[7];
    const float* wv_b = (const float*)d_in[8];
    const float* wo_w = (const float*)d_in[9];
    const float* wo_b = (const float*)d_in[10];
    float* out = (float*)d_out;

    const int SMEM_BYTES = NSTG * CHB + 64;   // 98368
    cudaFuncSetAttribute(mma_gemm, cudaFuncAttributeMaxDynamicSharedMemorySize, SMEM_BYTES);
    cudaFuncSetAttribute(kv_outer_mma, cudaFuncAttributeMaxDynamicSharedMemorySize, 65536);
    cudaFuncSetAttribute(qm_softmax_mma, cudaFuncAttributeMaxDynamicSharedMemorySize, 49152);

    prep_all<<<1024 + 4096, 256>>>(wq_w, wk_w, wv_w, wo_w, q, k, v);

    mma_gemm<<<dim3(24, 64), 256, SMEM_BYTES>>>(wq_b, wk_b, wv_b, nullptr, nullptr, 0);

    kv_outer_mma<<<dim3(BB * HH, KVP), 128, 65536>>>();   // includes last-block reduce
    qm_softmax_mma<<<dim3(BB * HH, KVP), 256, 49152>>>();

    mma_gemm<<<dim3(8, 64), 256, SMEM_BYTES>>>(nullptr, nullptr, nullptr, wo_b, out, 1);
}

// round 16
// speedup vs baseline: 1.0868x; 1.0868x over previous
#include <cuda_runtime.h>
#include <cuda_fp16.h>
#include <cstdint>

#define BB 4
#define SS 2048
#define DD 1024
#define HH 16
#define DKK 64
#define MR (BB*SS)   // 8192

#define MT 128
#define NT 128
#define NCH 32
#define TILEH 4096           // halves per 128x32 tile
#define TILEB 8192           // bytes per tile
#define CHB (4*TILEB)        // stage: Ahi|Alo|Bhi|Blo = 32KB
#define NSTG 3
#define KVP 16               // kv_outer partials

// ---------------- device scratch ----------------
__device__ __half g_wt[4][2][DD*DD];    // weight panels (x32 scaled, split hi/lo)
__device__ __half g_pan[4][2][MR*DD];   // activation panels: 0=q 1=k 2=v 3=softmax-out
__device__ float g_qh[MR*DD];
__device__ float g_kh[MR*DD];
__device__ float g_vh[MR*DD];
__device__ float g_Mpart[BB*HH*KVP][DKK*DKK];
__device__ float g_M[BB*HH][DKK*DKK];

// ---------------- helpers ----------------
__device__ __forceinline__ uint32_t smem_u32(const void* p) {
    uint32_t a;
    asm("{ .reg .u64 t; cvta.to.shared.u64 t, %1; cvt.u32.u64 %0, t; }" : "=r"(a) : "l"(p));
    return a;
}
#define MBAR_INIT(a, c) asm volatile("mbarrier.init.shared.b64 [%0], %1;" :: "r"(a), "r"(c) : "memory")
#define MBAR_WAIT(a, ph) do { \
    asm volatile("{\n\t.reg .pred P;\n\tWL%=:\n\t" \
        "mbarrier.try_wait.parity.shared.b64 P, [%0], %1;\n\t" \
        "@!P bra WL%=;\n\t}" :: "r"(a), "r"(ph) : "memory"); } while (0)
#define EXPECT_TX(a, n) asm volatile( \
    "mbarrier.arrive.expect_tx.shared.b64 _, [%0], %1;" :: "r"(a), "r"(n) : "memory")
#define BULK(dst, src, n, bar) asm volatile( \
    "cp.async.bulk.shared::cluster.global.mbarrier::complete_tx::bytes [%0], [%1], %2, [%3];" \
    :: "r"(dst), "l"(src), "r"(n), "r"(bar) : "memory")
#define LDSM4(r, a) asm volatile( \
    "ldmatrix.sync.aligned.m8n8.x4.shared.b16 {%0,%1,%2,%3}, [%4];" \
    : "=r"((r)[0]), "=r"((r)[1]), "=r"((r)[2]), "=r"((r)[3]) : "r"(a))
#define LDSM4T(r, a) asm volatile( \
    "ldmatrix.sync.aligned.m8n8.x4.trans.shared.b16 {%0,%1,%2,%3}, [%4];" \
    : "=r"((r)[0]), "=r"((r)[1]), "=r"((r)[2]), "=r"((r)[3]) : "r"(a))
#define MMAF16(d, a, b0, b1) asm volatile( \
    "mma.sync.aligned.m16n8k16.row.col.f32.f16.f16.f32 " \
    "{%0,%1,%2,%3}, {%4,%5,%6,%7}, {%8,%9}, {%0,%1,%2,%3};" \
    : "+f"((d)[0]), "+f"((d)[1]), "+f"((d)[2]), "+f"((d)[3]) \
    : "r"((a)[0]), "r"((a)[1]), "r"((a)[2]), "r"((a)[3]), "r"(b0), "r"(b1))

__device__ __forceinline__ uint32_t sw64(uint32_t off)  { return off ^ ((off >> 3) & 0x30); }
__device__ __forceinline__ uint32_t sw128(uint32_t off) { return off ^ ((off >> 3) & 0x70); }

__device__ __forceinline__ uint2 split4(float4 f, uint2& lo_out) {
    __half h0 = __float2half_rn(f.x), h1 = __float2half_rn(f.y);
    __half h2 = __float2half_rn(f.z), h3 = __float2half_rn(f.w);
    __half l0 = __float2half_rn(f.x - __half2float(h0));
    __half l1 = __float2half_rn(f.y - __half2float(h1));
    __half l2 = __float2half_rn(f.z - __half2float(h2));
    __half l3 = __float2half_rn(f.w - __half2float(h3));
    __half2 p0 = __halves2half2(h0, h1), p1 = __halves2half2(h2, h3);
    __half2 q0 = __halves2half2(l0, l1), q1 = __halves2half2(l2, l3);
    uint2 hi; hi.x = *(uint32_t*)&p0; hi.y = *(uint32_t*)&p1;
    lo_out.x = *(uint32_t*)&q0; lo_out.y = *(uint32_t*)&q1;
    return hi;
}

// ---------------------------------------------------------------------------
// fused prep:
//   blocks [0, 1024): one (tensor, head, 64-kq tile) each — smem transpose
//   blocks [1024, 5120): q/k/v split (coalesced both ways)
// ---------------------------------------------------------------------------
__global__ void prep_all(const float* __restrict__ wq, const float* __restrict__ wk,
                         const float* __restrict__ wv, const float* __restrict__ wo,
                         const float* __restrict__ q, const float* __restrict__ k,
                         const float* __restrict__ v) {
    int tid = threadIdx.x;
    if (blockIdx.x < 1024) {
        __shared__ float tile[64][65];
        int w = blockIdx.x >> 8;
        int h = (blockIdx.x >> 4) & 15;
        int kq0 = (blockIdx.x & 15) * 64;
        const float* W = (w == 0) ? wq : (w == 1) ? wk : (w == 2) ? wv : wo;
        if (w < 3) {
            #pragma unroll
            for (int i = 0; i < 16; i++) {
                int idx = tid + i * 256;
                int kqr = idx >> 6, dk = idx & 63;
                tile[dk][kqr] = W[h * (DD * DKK) + (kq0 + kqr) * DKK + dk];
            }
        } else {
            #pragma unroll
            for (int i = 0; i < 16; i++) {
                int idx = tid + i * 256;
                int dk = idx >> 6, kqr = idx & 63;
                tile[dk][kqr] = W[(h * 64 + dk) * DD + kq0 + kqr];
            }
        }
        __syncthreads();
        #pragma unroll
        for (int i = 0; i < 2; i++) {
            int idx = tid + i * 256;
            int dk = idx >> 3, chk = idx & 7;
            int kq = kq0 + chk * 8;
            int n = h * 64 + dk;
            float f[8];
            #pragma unroll
            for (int e = 0; e < 8; e++) f[e] = tile[dk][chk * 8 + e] * 32.0f;
            __half hi[8], lo[8];
            #pragma unroll
            for (int e = 0; e < 8; e++) {
                hi[e] = __float2half_rn(f[e]);
                lo[e] = __float2half_rn(f[e] - __half2float(hi[e]));
            }
            uint32_t off = (n & 127) * 64 + (kq & 31) * 2;
            size_t d = ((size_t)((n >> 7) * 32 + (kq >> 5))) * TILEH + (sw64(off) >> 1);
            *(uint4*)&g_wt[w][0][d] = *(uint4*)hi;
            *(uint4*)&g_wt[w][1][d] = *(uint4*)lo;
        }
    } else {
        int idx = (blockIdx.x - 1024) * 256 + tid;
        int m = idx >> 7;
        int k0 = (idx & 127) << 3;
        uint32_t off = (m & 127) * 64 + (k0 & 31) * 2;
        size_t d = ((size_t)((m >> 7) * 32 + (k0 >> 5))) * TILEH + (sw64(off) >> 1);
        size_t s = (size_t)m * DD + k0;
        const float* srcs[3] = { q + s, k + s, v + s };
        #pragma unroll
        for (int w = 0; w < 3; w++) {
            float f[8];
            *(float4*)&f[0] = *(const float4*)(srcs[w]);
            *(float4*)&f[4] = *(const float4*)(srcs[w] + 4);
            __half hi[8], lo[8];
            #pragma unroll
            for (int i = 0; i < 8; i++) {
                hi[i] = __float2half_rn(f[i]);
                lo[i] = __float2half_rn(f[i] - __half2float(hi[i]));
            }
            *(uint4*)&g_pan[w][0][d] = *(uint4*)hi;
            *(uint4*)&g_pan[w][1][d] = *(uint4*)lo;
        }
    }
}

// ---------------------------------------------------------------------------
// split fp16 mma.sync GEMM
// mode 0: fused QKV 3-pass; mode 1: wo 1-pass (A_hi x B_hi only; softmax probs
// tolerate dropping both lo terms: adds ~2.8e-4 relative rms, 3x under 1e-3)
// ---------------------------------------------------------------------------
__global__ __launch_bounds__(256, 2) void mma_gemm(
        const float* __restrict__ b0p, const float* __restrict__ b1p,
        const float* __restrict__ b2p, const float* __restrict__ bwp,
        float* __restrict__ Oout, int mode) {
    extern __shared__ char smem[];
    int widx, nIdx;
    const float* bias;
    float* C;
    if (mode == 0) {
        widx = blockIdx.x >> 3;
        nIdx = blockIdx.x & 7;
        bias = (widx == 0) ? b0p : (widx == 1) ? b1p : b2p;
        C = (widx == 0) ? g_qh : (widx == 1) ? g_kh : g_vh;
    } else {
        widx = 3;
        nIdx = blockIdx.x;
        bias = bwp;
        C = Oout;
    }
    const __half* Ahi = g_pan[widx][0];
    const __half* Alo = g_pan[widx][1];
    const __half* Bhi = g_wt[widx][0];
    const __half* Blo = g_wt[widx][1];

    const uint32_t s0 = smem_u32(smem);
    const uint32_t mb = s0 + NSTG * CHB;

    const int tid = threadIdx.x;
    const int wid = tid >> 5, lane = tid & 31;
    const int bm = blockIdx.y * MT, bn = nIdx * NT;
    const int m0 = (wid >> 2) * 64;
    const int n0 = (wid & 3) * 32;

    if (tid == 0) { MBAR_INIT(mb, 1); MBAR_INIT(mb + 8, 1); MBAR_INIT(mb + 16, 1); }
    __syncthreads();

    const uint32_t stage_bytes = (mode == 0) ? 4u * TILEB : 2u * TILEB;
    auto issue = [&](int ch, int stg) {
        uint32_t sb = s0 + stg * CHB;
        uint32_t bar = mb + stg * 8;
        EXPECT_TX(bar, stage_bytes);
        const __half* a0 = Ahi + ((size_t)(blockIdx.y * 32 + ch)) * TILEH;
        const __half* w0 = Bhi + ((size_t)(nIdx * 32 + ch)) * TILEH;
        BULK(sb,             a0, TILEB, bar);
        BULK(sb + 2 * TILEB, w0, TILEB, bar);
        if (mode == 0) {
            const __half* a1 = Alo + ((size_t)(blockIdx.y * 32 + ch)) * TILEH;
            const __half* w1 = Blo + ((size_t)(nIdx * 32 + ch)) * TILEH;
            BULK(sb + TILEB,     a1, TILEB, bar);
            BULK(sb + 3 * TILEB, w1, TILEB, bar);
        }
    };
    if (tid == 0) { issue(0, 0); issue(1, 1); }

    const int rowA = m0 + (lane & 7) + ((lane >> 3) & 1) * 8;
    const uint32_t cA = ((lane >> 4) & 1) * 16;
    const uint32_t xswA = (uint32_t)(rowA & 6) << 3;
    const uint32_t aRow = (uint32_t)rowA * 64;
    const int rowB = n0 + ((lane >> 4) << 3) + (lane & 7);
    const uint32_t cB = ((lane >> 3) & 1) * 16;
    const uint32_t xswB = (uint32_t)(rowB & 6) << 3;
    const uint32_t bRow = (uint32_t)rowB * 64;

    float acc[4][4][4];
    #pragma unroll
    for (int i = 0; i < 4; i++)
        #pragma unroll
        for (int j = 0; j < 4; j++)
            #pragma unroll
            for (int r = 0; r < 4; r++) acc[i][j][r] = 0.0f;

    for (int c = 0; c < NCH; ++c) {
        int stg = c % 3;
        uint32_t sb = s0 + stg * CHB;
        MBAR_WAIT(mb + stg * 8, (c / 3) & 1);
        if (tid == 0 && c + 2 < NCH) issue(c + 2, (c + 2) % 3);

        #pragma unroll
        for (int ks = 0; ks < 2; ks++) {
            const uint32_t aoff = aRow + (((uint32_t)(ks * 32) + cA) ^ xswA);
            const uint32_t boff = bRow + (((uint32_t)(ks * 32) + cB) ^ xswB);
            uint32_t ah[4][4], al[4][4], bh[2][4], bl[2][4];
            #pragma unroll
            for (int i = 0; i < 4; i++) LDSM4(ah[i], sb + aoff + i * 1024);
            #pragma unroll
            for (int g = 0; g < 2; g++) LDSM4(bh[g], sb + 2 * TILEB + boff + g * 1024);
            #pragma unroll
            for (int i = 0; i < 4; i++) {
                MMAF16(acc[i][0], ah[i], bh[0][0], bh[0][1]);
                MMAF16(acc[i][1], ah[i], bh[0][2], bh[0][3]);
                MMAF16(acc[i][2], ah[i], bh[1][0], bh[1][1]);
                MMAF16(acc[i][3], ah[i], bh[1][2], bh[1][3]);
            }
            if (mode == 0) {
                #pragma unroll
                for (int g = 0; g < 2; g++) LDSM4(bl[g], sb + 3 * TILEB + boff + g * 1024);
                #pragma unroll
                for (int i = 0; i < 4; i++) {
                    MMAF16(acc[i][0], ah[i], bl[0][0], bl[0][1]);
                    MMAF16(acc[i][1], ah[i], bl[0][2], bl[0][3]);
                    MMAF16(acc[i][2], ah[i], bl[1][0], bl[1][1]);
                    MMAF16(acc[i][3], ah[i], bl[1][2], bl[1][3]);
                }
                #pragma unroll
                for (int i = 0; i < 4; i++) LDSM4(al[i], sb + TILEB + aoff + i * 1024);
                #pragma unroll
                for (int i = 0; i < 4; i++) {
                    MMAF16(acc[i][0], al[i], bh[0][0], bh[0][1]);
                    MMAF16(acc[i][1], al[i], bh[0][2], bh[0][3]);
                    MMAF16(acc[i][2], al[i], bh[1][0], bh[1][1]);
                    MMAF16(acc[i][3], al[i], bh[1][2], bh[1][3]);
                }
            }
        }
        __syncthreads();
    }

    #pragma unroll
    for (int i = 0; i < 4; i++) {
        int row0 = bm + m0 + i * 16 + (lane >> 2);
        #pragma unroll
        for (int jj = 0; jj < 4; jj++) {
            int col = bn + n0 + jj * 8 + (lane & 3) * 2;
            float2 bv = *(const float2*)(bias + col);
            float2 r0, r1;
            r0.x = acc[i][jj][0] * 0.03125f + bv.x;  r0.y = acc[i][jj][1] * 0.03125f + bv.y;
            r1.x = acc[i][jj][2] * 0.03125f + bv.x;  r1.y = acc[i][jj][3] * 0.03125f + bv.y;
            *(float2*)(C + (size_t)row0 * DD + col) = r0;
            *(float2*)(C + (size_t)(row0 + 8) * DD + col) = r1;
        }
    }
}

// ---------------------------------------------------------------------------
// kv_outer via tensor cores (R14 version): in-kernel convert, 3-pass fp16.
// ---------------------------------------------------------------------------
__global__ __launch_bounds__(128) void kv_outer_mma() {
    extern __shared__ char smem[];
    const uint32_t sK0 = smem_u32(smem);
    const uint32_t sK1 = sK0 + 16384;
    const uint32_t sV0 = sK0 + 32768;
    const uint32_t sV1 = sK0 + 49152;

    int bh = blockIdx.x;
    int b = bh >> 4, h = bh & 15;
    int sy = blockIdx.y;
    int tid = threadIdx.x;
    int wid = tid >> 5, lane = tid & 31;
    int wm = wid >> 1, wn = wid & 1;

    const float* Kg = g_kh + ((size_t)b * SS + sy * 128) * DD + h * DKK;
    const float* Vg = g_vh + ((size_t)b * SS + sy * 128) * DD + h * DKK;

    #pragma unroll
    for (int i = 0; i < 16; i++) {
        int idx = tid + i * 128;
        int s = idx >> 4, c4 = (idx & 15) << 2;
        uint32_t sw = sw128((uint32_t)s * 128 + c4 * 2);
        uint2 lo;
        uint2 hi = split4(*(const float4*)(Kg + (size_t)s * DD + c4), lo);
        *(uint2*)(smem + sw) = hi;
        *(uint2*)(smem + 16384 + sw) = lo;
        hi = split4(*(const float4*)(Vg + (size_t)s * DD + c4), lo);
        *(uint2*)(smem + 32768 + sw) = hi;
        *(uint2*)(smem + 49152 + sw) = lo;
    }
    __syncthreads();

    const uint32_t a_srow = (uint32_t)((lane & 7) + ((lane >> 4) << 3));
    const uint32_t a_xsw = (a_srow & 7) << 4;
    uint32_t aOff[2];
    #pragma unroll
    for (int mi = 0; mi < 2; mi++) {
        uint32_t col = (uint32_t)(wm * 32 + mi * 16 + ((lane >> 3) & 1) * 8);
        aOff[mi] = a_srow * 128 + ((col * 2) ^ a_xsw);
    }
    const uint32_t b_srow = (uint32_t)((lane & 7) + (((lane >> 3) & 1) << 3));
    const uint32_t b_xsw = (b_srow & 7) << 4;
    uint32_t bOff[2];
    #pragma unroll
    for (int g = 0; g < 2; g++) {
        uint32_t col = (uint32_t)(wn * 32 + g * 16 + ((lane >> 4) & 1) * 8);
        bOff[g] = b_srow * 128 + ((col * 2) ^ b_xsw);
    }

    float acc[2][4][4];
    #pragma unroll
    for (int i = 0; i < 2; i++)
        #pragma unroll
        for (int j = 0; j < 4; j++)
            #pragma unroll
            for (int r = 0; r < 4; r++) acc[i][j][r] = 0.0f;

    #pragma unroll
    for (int st = 0; st < 8; st++) {
        uint32_t base = (uint32_t)st * 2048;
        uint32_t kh[2][4], kl[2][4], vh[2][4], vl[2][4];
        #pragma unroll
        for (int mi = 0; mi < 2; mi++) LDSM4T(kh[mi], sK0 + base + aOff[mi]);
        #pragma unroll
        for (int g = 0; g < 2; g++)  LDSM4T(vh[g], sV0 + base + bOff[g]);
        #pragma unroll
        for (int mi = 0; mi < 2; mi++) {
            MMAF16(acc[mi][0], kh[mi], vh[0][0], vh[0][1]);
            MMAF16(acc[mi][1], kh[mi], vh[0][2], vh[0][3]);
            MMAF16(acc[mi][2], kh[mi], vh[1][0], vh[1][1]);
            MMAF16(acc[mi][3], kh[mi], vh[1][2], vh[1][3]);
        }
        #pragma unroll
        for (int g = 0; g < 2; g++)  LDSM4T(vl[g], sV1 + base + bOff[g]);
        #pragma unroll
        for (int mi = 0; mi < 2; mi++) {
            MMAF16(acc[mi][0], kh[mi], vl[0][0], vl[0][1]);
            MMAF16(acc[mi][1], kh[mi], vl[0][2], vl[0][3]);
            MMAF16(acc[mi][2], kh[mi], vl[1][0], vl[1][1]);
            MMAF16(acc[mi][3], kh[mi], vl[1][2], vl[1][3]);
        }
        #pragma unroll
        for (int mi = 0; mi < 2; mi++) LDSM4T(kl[mi], sK1 + base + aOff[mi]);
        #pragma unroll
        for (int mi = 0; mi < 2; mi++) {
            MMAF16(acc[mi][0], kl[mi], vh[0][0], vh[0][1]);
            MMAF16(acc[mi][1], kl[mi], vh[0][2], vh[0][3]);
            MMAF16(acc[mi][2], kl[mi], vh[1][0], vh[1][1]);
            MMAF16(acc[mi][3], kl[mi], vh[1][2], vh[1][3]);
        }
    }

    float* Mout = g_Mpart[bh * KVP + sy];
    #pragma unroll
    for (int mi = 0; mi < 2; mi++) {
        int row = wm * 32 + mi * 16 + (lane >> 2);
        #pragma unroll
        for (int ng = 0; ng < 4; ng++) {
            int col = wn * 32 + ng * 8 + (lane & 3) * 2;
            float2 p0, p1;
            p0.x = acc[mi][ng][0]; p0.y = acc[mi][ng][1];
            p1.x = acc[mi][ng][2]; p1.y = acc[mi][ng][3];
            *(float2*)&Mout[row * DKK + col]       = p0;
            *(float2*)&Mout[(row + 8) * DKK + col] = p1;
        }
    }
}

// flat 256-block reduce
__global__ __launch_bounds__(256) void reduce_M() {
    int t = blockIdx.x * 256 + threadIdx.x;
    int bh = t >> 10;
    int e4 = t & 1023;
    float4 s = make_float4(0.f, 0.f, 0.f, 0.f);
    #pragma unroll
    for (int c = 0; c < KVP; c++) {
        float4 p = *(const float4*)&g_Mpart[bh * KVP + c][e4 * 4];
        s.x += p.x; s.y += p.y; s.z += p.z; s.w += p.w;
    }
    *(float4*)&g_M[bh][e4 * 4] = s;
}

// ---------------------------------------------------------------------------
// qm_softmax via tensor cores (unchanged)
// ---------------------------------------------------------------------------
__global__ __launch_bounds__(256) void qm_softmax_mma() {
    extern __shared__ char smem[];
    const uint32_t sQ0 = smem_u32(smem);
    const uint32_t sQ1 = sQ0 + 16384;
    const uint32_t sM0 = sQ0 + 32768;
    const uint32_t sM1 = sQ0 + 40960;

    int bh = blockIdx.x;
    int b = bh >> 4, h = bh & 15;
    int sy = blockIdx.y;
    int tid = threadIdx.x;
    int wid = tid >> 5, lane = tid & 31;

    #pragma unroll
    for (int i = 0; i < 4; i++) {
        int idx = tid + i * 256;
        int j = idx >> 4, c4 = (idx & 15) << 2;
        uint32_t sw = sw128((uint32_t)j * 128 + c4 * 2);
        uint2 lo;
        uint2 hi = split4(*(const float4*)&g_M[bh][j * DKK + c4], lo);
        *(uint2*)(smem + 32768 + sw) = hi;
        *(uint2*)(smem + 40960 + sw) = lo;
    }
    const float* Qg = g_qh + ((size_t)b * SS + sy * 128) * DD + h * DKK;
    #pragma unroll
    for (int i = 0; i < 8; i++) {
        int idx = tid + i * 256;
        int s = idx >> 4, c4 = (idx & 15) << 2;
        uint32_t sw = sw128((uint32_t)s * 128 + c4 * 2);
        uint2 lo;
        uint2 hi = split4(*(const float4*)(Qg + (size_t)s * DD + c4), lo);
        *(uint2*)(smem + sw) = hi;
        *(uint2*)(smem + 16384 + sw) = lo;
    }
    __syncthreads();

    const int a_row = wid * 16 + (lane & 7) + ((lane >> 3) & 1) * 8;
    const uint32_t a_base = (uint32_t)a_row * 128;
    const uint32_t a_xsw = ((uint32_t)a_row & 7) << 4;
    const uint32_t a_c = ((lane >> 4) & 1) * 16;
    const uint32_t b_srow = (uint32_t)((lane & 7) + (((lane >> 3) & 1) << 3));
    const uint32_t b_xsw = (b_srow & 7) << 4;
    uint32_t bOff[4];
    #pragma unroll
    for (int g = 0; g < 4; g++) {
        uint32_t col = (uint32_t)(g * 16 + ((lane >> 4) & 1) * 8);
        bOff[g] = b_srow * 128 + ((col * 2) ^ b_xsw);
    }

    float acc[8][4];
    #pragma unroll
    for (int j = 0; j < 8; j++)
        #pragma unroll
        for (int r = 0; r < 4; r++) acc[j][r] = 0.0f;

    #pragma unroll
    for (int st = 0; st < 4; st++) {
        uint32_t aoff = a_base + (((uint32_t)st * 32 + a_c) ^ a_xsw);
        uint32_t bbase = (uint32_t)st * 2048;
        uint32_t qh4[4], ql4[4], mh[4][4], ml[4][4];
        LDSM4(qh4, sQ0 + aoff);
        #pragma unroll
        for (int g = 0; g < 4; g++) LDSM4T(mh[g], sM0 + bbase + bOff[g]);
        #pragma unroll
        for (int g = 0; g < 4; g++) {
            MMAF16(acc[g * 2 + 0], qh4, mh[g][0], mh[g][1]);
            MMAF16(acc[g * 2 + 1], qh4, mh[g][2], mh[g][3]);
        }
        #pragma unroll
        for (int g = 0; g < 4; g++) LDSM4T(ml[g], sM1 + bbase + bOff[g]);
        #pragma unroll
        for (int g = 0; g < 4; g++) {
            MMAF16(acc[g * 2 + 0], qh4, ml[g][0], ml[g][1]);
            MMAF16(acc[g * 2 + 1], qh4, ml[g][2], ml[g][3]);
        }
        LDSM4(ql4, sQ1 + aoff);
        #pragma unroll
        for (int g = 0; g < 4; g++) {
            MMAF16(acc[g * 2 + 0], ql4, mh[g][0], mh[g][1]);
            MMAF16(acc[g * 2 + 1], ql4, mh[g][2], mh[g][3]);
        }
    }

    float mx0 = -1e30f, mx1 = -1e30f;
    #pragma unroll
    for (int f = 0; f < 8; f++) {
        acc[f][0] *= 0.125f; acc[f][1] *= 0.125f;
        acc[f][2] *= 0.125f; acc[f][3] *= 0.125f;
        mx0 = fmaxf(mx0, fmaxf(acc[f][0], acc[f][1]));
        mx1 = fmaxf(mx1, fmaxf(acc[f][2], acc[f][3]));
    }
    #pragma unroll
    for (int o = 1; o <= 2; o <<= 1) {
        mx0 = fmaxf(mx0, __shfl_xor_sync(0xffffffffu, mx0, o));
        mx1 = fmaxf(mx1, __shfl_xor_sync(0xffffffffu, mx1, o));
    }
    float sm0 = 0.0f, sm1 = 0.0f;
    #pragma unroll
    for (int f = 0; f < 8; f++) {
        acc[f][0] = __expf(acc[f][0] - mx0); acc[f][1] = __expf(acc[f][1] - mx0);
        acc[f][2] = __expf(acc[f][2] - mx1); acc[f][3] = __expf(acc[f][3] - mx1);
        sm0 += acc[f][0] + acc[f][1];
        sm1 += acc[f][2] + acc[f][3];
    }
    #pragma unroll
    for (int o = 1; o <= 2; o <<= 1) {
        sm0 += __shfl_xor_sync(0xffffffffu, sm0, o);
        sm1 += __shfl_xor_sync(0xffffffffu, sm1, o);
    }
    float inv0 = 1.0f / sm0, inv1 = 1.0f / sm1;

    int mt = b * 16 + sy;
    int prow0 = wid * 16 + (lane >> 2);
    #pragma unroll
    for (int f = 0; f < 8; f++) {
        int cc = f * 8 + (lane & 3) * 2;
        int chunk = 2 * h + (cc >> 5);
        uint32_t cwi = (uint32_t)(cc & 31);
        size_t tbase = ((size_t)(mt * 32 + chunk)) * TILEH;
        uint32_t off0 = sw64((uint32_t)prow0 * 64 + cwi * 2) >> 1;
        uint32_t off1 = sw64((uint32_t)(prow0 + 8) * 64 + cwi * 2) >> 1;
        __half2 v0 = __halves2half2(__float2half_rn(acc[f][0] * inv0),
                                    __float2half_rn(acc[f][1] * inv0));
        __half2 v1 = __halves2half2(__float2half_rn(acc[f][2] * inv1),
                                    __float2half_rn(acc[f][3] * inv1));
        *(__half2*)&g_pan[3][0][tbase + off0] = v0;
        *(__half2*)&g_pan[3][0][tbase + off1] = v1;
    }
}

// ---------------------------------------------------------------------------
extern "C" void kernel_launch(void* const* d_in, const int* in_sizes, int n_in,
                              void* d_out, int out_size) {
    const float* q    = (const float*)d_in[0];
    const float* k    = (const float*)d_in[1];
    const float* v    = (const float*)d_in[2];
    const float* wq_w = (const float*)d_in[3];
    const float* wq_b = (const float*)d_in[4];
    const float* wk_w = (const float*)d_in[5];
    const float* wk_b = (const float*)d_in[6];
    const float* wv_w = (const float*)d_in[7];
    const float* wv_b = (const float*)d_in[8];
    const float* wo_w = (const float*)d_in[9];
    const float* wo_b = (const float*)d_in[10];
    float* out = (float*)d_out;

    const int SMEM_BYTES = NSTG * CHB + 64;   // 98368
    cudaFuncSetAttribute(mma_gemm, cudaFuncAttributeMaxDynamicSharedMemorySize, SMEM_BYTES);
    cudaFuncSetAttribute(kv_outer_mma, cudaFuncAttributeMaxDynamicSharedMemorySize, 65536);
    cudaFuncSetAttribute(qm_softmax_mma, cudaFuncAttributeMaxDynamicSharedMemorySize, 49152);

    prep_all<<<1024 + 4096, 256>>>(wq_w, wk_w, wv_w, wo_w, q, k, v);

    mma_gemm<<<dim3(24, 64), 256, SMEM_BYTES>>>(wq_b, wk_b, wv_b, nullptr, nullptr, 0);

    kv_outer_mma<<<dim3(BB * HH, KVP), 128, 65536>>>();
    reduce_M<<<256, 256>>>();
    qm_softmax_mma<<<dim3(BB * HH, KVP), 256, 49152>>>();

    mma_gemm<<<dim3(8, 64), 256, SMEM_BYTES>>>(nullptr, nullptr, nullptr, wo_b, out, 1);
}